// round 9
// baseline (speedup 1.0000x reference)
#include <cuda_runtime.h>

// CircleProjectionLayer: z = center + (x-center) * min(1, 1/||x-center||)
// B = 8388608 points, [B,3] f32. HBM stream: 192MB read + 96MB write.
//
// R8: two SEPARATED quads per thread. Each LDG.128 keeps R1's proven 48B
// lane stride (1536B warp footprint, clean sector merging), but the warp
// now issues a 12-load read burst then a 6-store write burst — double R1's
// same-direction run length, testing the DRAM read<->write turnaround
// theory without R2/R6's 96B-stride footprint confound.
//
// Thread t of block b handles quads (b*512 + t) and (b*512 + 256 + t).

__global__ void __launch_bounds__(256)
circle_proj_kernel(const float4* __restrict__ x4,
                   const float4* __restrict__ c4,
                   float4* __restrict__ o4)
{
    int t = threadIdx.x;
    long q0 = (long)blockIdx.x * 512 + t;        // first quad
    long q1 = q0 + 256;                           // second quad
    long a = 3L * q0;                             // float4 base of quad 0
    long b = 3L * q1;                             // float4 base of quad 1

    // ---- long read burst: 12 x LDG.128, all 48B lane stride ----
    float4 xa0 = x4[a + 0];
    float4 xa1 = x4[a + 1];
    float4 xa2 = x4[a + 2];
    float4 xb0 = x4[b + 0];
    float4 xb1 = x4[b + 1];
    float4 xb2 = x4[b + 2];
    float4 ca0 = c4[a + 0];
    float4 ca1 = c4[a + 1];
    float4 ca2 = c4[a + 2];
    float4 cb0 = c4[b + 0];
    float4 cb1 = c4[b + 1];
    float4 cb2 = c4[b + 2];

    float xs[24] = {xa0.x, xa0.y, xa0.z, xa0.w,
                    xa1.x, xa1.y, xa1.z, xa1.w,
                    xa2.x, xa2.y, xa2.z, xa2.w,
                    xb0.x, xb0.y, xb0.z, xb0.w,
                    xb1.x, xb1.y, xb1.z, xb1.w,
                    xb2.x, xb2.y, xb2.z, xb2.w};
    float cs[24] = {ca0.x, ca0.y, ca0.z, ca0.w,
                    ca1.x, ca1.y, ca1.z, ca1.w,
                    ca2.x, ca2.y, ca2.z, ca2.w,
                    cb0.x, cb0.y, cb0.z, cb0.w,
                    cb1.x, cb1.y, cb1.z, cb1.w,
                    cb2.x, cb2.y, cb2.z, cb2.w};
    float os[24];

#pragma unroll
    for (int p = 0; p < 8; p++) {
        float dx = xs[3 * p + 0] - cs[3 * p + 0];
        float dy = xs[3 * p + 1] - cs[3 * p + 1];
        float dz = xs[3 * p + 2] - cs[3 * p + 2];
        float n2 = fmaf(dx, dx, fmaf(dy, dy, dz * dz));
        // RADIUS = 1: scale = min(1, 1/||d||); rsqrtf(0)=inf -> scale=1 -> z=x.
        float s = fminf(1.0f, rsqrtf(n2));
        os[3 * p + 0] = fmaf(dx, s, cs[3 * p + 0]);
        os[3 * p + 1] = fmaf(dy, s, cs[3 * p + 1]);
        os[3 * p + 2] = fmaf(dz, s, cs[3 * p + 2]);
    }

    // ---- long write burst: 6 x STG.128, all 48B lane stride ----
    o4[a + 0] = make_float4(os[0],  os[1],  os[2],  os[3]);
    o4[a + 1] = make_float4(os[4],  os[5],  os[6],  os[7]);
    o4[a + 2] = make_float4(os[8],  os[9],  os[10], os[11]);
    o4[b + 0] = make_float4(os[12], os[13], os[14], os[15]);
    o4[b + 1] = make_float4(os[16], os[17], os[18], os[19]);
    o4[b + 2] = make_float4(os[20], os[21], os[22], os[23]);
}

extern "C" void kernel_launch(void* const* d_in, const int* in_sizes, int n_in,
                              void* d_out, int out_size)
{
    const float4* x4 = (const float4*)d_in[0];   // x: [B,3] f32
    const float4* c4 = (const float4*)d_in[1];   // center: [B,3] f32
    float4* o4 = (float4*)d_out;

    int n_elems = in_sizes[0];          // B*3 = 25165824
    int n_points = n_elems / 3;         // 8388608
    int n_quads = n_points / 4;         // 2097152
    int blocks = n_quads / 512;         // 4096, exact (each block: 512 quads)

    circle_proj_kernel<<<blocks, 256>>>(x4, c4, o4);
}

// round 10
// speedup vs baseline: 1.0765x; 1.0765x over previous
#include <cuda_runtime.h>

// CircleProjectionLayer: z = center + (x-center) * min(1, 1/||x-center||)
// B = 8388608 points, [B,3] f32. HBM stream: 192MB read + 96MB write.
//
// R9: R1 structure exactly (4 points/thread, 6 x LDG.128 @ 48B lane stride,
// default caching — proven optimal shape) with 512-thread blocks. Per the
// B300 multi-CTA spread model, halving CTAs/SM (8 -> 4) at constant warp
// count halves oe*MLP_p1 (48 -> 24), cutting cross-CTA L1tex-queue
// contention / tail-CTA spread. Zero cost otherwise (same regs, same MLP).

__global__ void __launch_bounds__(512)
circle_proj_kernel(const float4* __restrict__ x4,
                   const float4* __restrict__ c4,
                   float4* __restrict__ o4,
                   int n_quads)  // groups of 4 points = 3 float4 each
{
    int i = blockIdx.x * blockDim.x + threadIdx.x;
    if (i >= n_quads) return;

    long base = 3L * i;

    // Front-batch all 6 loads (MLP=6) before any math.
    float4 xa = x4[base + 0];
    float4 xb = x4[base + 1];
    float4 xc = x4[base + 2];
    float4 ca = c4[base + 0];
    float4 cb = c4[base + 1];
    float4 cc = c4[base + 2];

    float xs[12] = {xa.x, xa.y, xa.z, xa.w,
                    xb.x, xb.y, xb.z, xb.w,
                    xc.x, xc.y, xc.z, xc.w};
    float cs[12] = {ca.x, ca.y, ca.z, ca.w,
                    cb.x, cb.y, cb.z, cb.w,
                    cc.x, cc.y, cc.z, cc.w};
    float os[12];

#pragma unroll
    for (int p = 0; p < 4; p++) {
        float dx = xs[3 * p + 0] - cs[3 * p + 0];
        float dy = xs[3 * p + 1] - cs[3 * p + 1];
        float dz = xs[3 * p + 2] - cs[3 * p + 2];
        float n2 = fmaf(dx, dx, fmaf(dy, dy, dz * dz));
        // RADIUS = 1: scale = min(1, 1/||d||); rsqrtf(0)=inf -> scale=1 -> z=x.
        float s = fminf(1.0f, rsqrtf(n2));
        os[3 * p + 0] = fmaf(dx, s, cs[3 * p + 0]);
        os[3 * p + 1] = fmaf(dy, s, cs[3 * p + 1]);
        os[3 * p + 2] = fmaf(dz, s, cs[3 * p + 2]);
    }

    o4[base + 0] = make_float4(os[0], os[1], os[2],  os[3]);
    o4[base + 1] = make_float4(os[4], os[5], os[6],  os[7]);
    o4[base + 2] = make_float4(os[8], os[9], os[10], os[11]);
}

extern "C" void kernel_launch(void* const* d_in, const int* in_sizes, int n_in,
                              void* d_out, int out_size)
{
    const float4* x4 = (const float4*)d_in[0];   // x: [B,3] f32
    const float4* c4 = (const float4*)d_in[1];   // center: [B,3] f32
    float4* o4 = (float4*)d_out;

    int n_elems = in_sizes[0];          // B*3 = 25165824
    int n_points = n_elems / 3;         // 8388608
    int n_quads = n_points / 4;         // 2097152

    int threads = 512;
    int blocks = (n_quads + threads - 1) / threads;  // 4096
    circle_proj_kernel<<<blocks, threads>>>(x4, c4, o4, n_quads);
}